// round 3
// baseline (speedup 1.0000x reference)
#include <cuda_runtime.h>

#define B_   16
#define T_   256
#define NTR_ 1024
#define NTE_ 256
#define NALL 1280
#define NG   8            // n's per block (loop)

#define L2E      1.4426950408889634f
#define LOG2_L2E 0.5287663729448977f

typedef unsigned long long u64;

__device__ __forceinline__ float ex2(float x) {
    float r; asm("ex2.approx.f32 %0, %1;" : "=f"(r) : "f"(x)); return r;
}
__device__ __forceinline__ u64 pk(float lo, float hi) {
    u64 r; asm("mov.b64 %0, {%1,%2};" : "=l"(r) : "f"(lo), "f"(hi)); return r;
}
__device__ __forceinline__ void upk(u64 v, float& lo, float& hi) {
    asm("mov.b64 {%0,%1}, %2;" : "=f"(lo), "=f"(hi) : "l"(v));
}
__device__ __forceinline__ u64 f2fma(u64 a, u64 b, u64 c) {
    u64 d; asm("fma.rn.f32x2 %0, %1, %2, %3;" : "=l"(d) : "l"(a), "l"(b), "l"(c)); return d;
}
__device__ __forceinline__ u64 f2mul(u64 a, u64 b) {
    u64 d; asm("mul.rn.f32x2 %0, %1, %2;" : "=l"(d) : "l"(a), "l"(b)); return d;
}
__device__ __forceinline__ u64 f2add(u64 a, u64 b) {
    u64 d; asm("add.rn.f32x2 %0, %1, %2;" : "=l"(d) : "l"(a), "l"(b)); return d;
}
// Volatile 128-bit shared load: defeats LICM so the bicubic table never
// occupies long-lived registers.
__device__ __forceinline__ void ldsC(unsigned addr, u64& a, u64& b) {
    asm volatile("ld.shared.v2.u64 {%0,%1}, [%2];" : "=l"(a), "=l"(b) : "r"(addr));
}

// Block = (b, group of NG n's). 128 threads, each owning the adjacent t-pair
// (2*tid, 2*tid+1) packed into f32x2 lanes. Loop over NG n's; per-n constants
// and the bicubic table live in smem as pre-duplicated / broadcast u64 pairs.
__global__ void __launch_bounds__(128, 8)
decoder_fused(const float* __restrict__ z0,
              const float* __restrict__ z1,
              const float* __restrict__ coeff0,
              const float* __restrict__ mean0,
              const float* __restrict__ log_var0,
              const float* __restrict__ coeff1,
              const float* __restrict__ mean1,
              const float* __restrict__ log_var1,
              const float* __restrict__ rf_tr0,
              const float* __restrict__ rf_tr1,
              const float* __restrict__ rf_te0,
              const float* __restrict__ rf_te1,
              const float* __restrict__ ew_tr,
              const float* __restrict__ ew_te,
              const float* __restrict__ lfs_tr,
              const float* __restrict__ lfs_te,
              float* __restrict__ out)
{
    __shared__ float4 sN[NG][5];   // per-n consts, duplicated pairs
    __shared__ u64    sC[16];      // bicubic coeffs, duplicated pairs
    __shared__ float  sG[4];       // kxl, kyl, axl, ayl

    const int tid = threadIdx.x;
    const int bid = blockIdx.x;
    const int b   = bid / (NALL / NG);
    const int ng  = bid % (NALL / NG);
    const int n0  = ng * NG;

    // ---- in-block constant prep ----
    if (tid < NG) {
        int n = n0 + tid;
        int nn; const float *rf0, *rf1, *ew, *lfs;
        if (n < NTR_) { nn = n;        rf0 = rf_tr0; rf1 = rf_tr1; ew = ew_tr; lfs = lfs_tr; }
        else          { nn = n - NTR_; rf0 = rf_te0; rf1 = rf_te1; ew = ew_te; lfs = lfs_te; }

        // Torus (K0=1,L0=1), natural-log units:
        // resp0 = A*exp(p*s + q*c);  e0 = exp(resp0) = exp(A)*exp(A*expm1(w))
        float mu  = mean0[0];
        float ms  = sinf(mu) - sinf(rf0[nn]);
        float mc  = cosf(mu) - cosf(rf0[nn]);
        float v0  = expf(log_var0[0]);
        float iv0 = 1.0f / (v0 * v0);
        float p   = 2.0f * ms * iv0;
        float q   = 2.0f * mc * iv0;
        float A   = coeff0[0] * expf(-(1.0f + ms * ms + mc * mc) * iv0);
        float EA  = expf(A);

        float e0w = ew[nn * 2], e1w = ew[nn * 2 + 1];
        float mx  = fmaxf(e0w, e1w);
        float ea  = expf(e0w - mx), eb = expf(e1w - mx);
        float scl = expf(lfs[nn]) / (ea + eb);
        float w0  = ea * scl, w1 = eb * scl;
        float W0E = w0 * EA;

        float dx  = mean1[8] - mean1[0];
        float dy  = mean1[3] - mean1[1];
        float vx  = expf(log_var1[0]), vy = expf(log_var1[1]);
        float ivx = 1.0f / (vx * vx),  ivy = 1.0f / (vy * vy);
        float axl = ivx * L2E,         ayl = ivy * L2E;
        float kxl = 2.0f * dx * ivx * L2E, kyl = 2.0f * dy * ivy * L2E;
        float rx  = rf1[nn * 2 + 0] - mean1[0];
        float ry  = rf1[nn * 2 + 1] - mean1[1];
        float Rx  = exp2f(kxl * rx), Ry = exp2f(kyl * ry);
        float Px  = -2.0f * axl * rx, Py = -2.0f * ayl * ry;
        float Ln  = -axl * rx * rx - ayl * ry * ry;

        sN[tid][0] = make_float4(p,  p,  q,   q);
        sN[tid][1] = make_float4(A,  A,  W0E, W0E);
        sN[tid][2] = make_float4(Rx, Rx, Ry,  Ry);
        sN[tid][3] = make_float4(Px, Px, Py,  Py);
        sN[tid][4] = make_float4(Ln, Ln, w1,  w1);
    } else if (tid >= 32 && tid < 48) {
        int e = tid - 32;
        int i = e & 3, j = e >> 2;
        float dx  = mean1[8] - mean1[0];
        float dy  = mean1[3] - mean1[1];
        float vx  = expf(log_var1[0]), vy = expf(log_var1[1]);
        float ivx = 1.0f / (vx * vx),  ivy = 1.0f / (vy * vy);
        float v = coeff1[i * 4 + j] *
                  expf(-(float)(i * i) * dx * dx * ivx - (float)(j * j) * dy * dy * ivy);
        sC[e] = pk(v, v);
    } else if (tid == 64) {
        float dx  = mean1[8] - mean1[0];
        float dy  = mean1[3] - mean1[1];
        float vx  = expf(log_var1[0]), vy = expf(log_var1[1]);
        float ivx = 1.0f / (vx * vx),  ivy = 1.0f / (vy * vy);
        sG[0] = 2.0f * dx * ivx * L2E;   // kxl
        sG[1] = 2.0f * dy * ivy * L2E;   // kyl
        sG[2] = ivx * L2E;               // axl
        sG[3] = ivy * L2E;               // ayl
    }
    __syncthreads();

    const float kxl = sG[0], kyl = sG[1], axl = sG[2], ayl = sG[3];

    // ---- per-thread adjacent t-pair terms ----
    const int t0 = 2 * tid;
    float2 zz = ((const float2*)z0)[(b * T_ >> 1) + tid];           // z0[t0], z0[t0+1]
    float4 zv = ((const float4*)z1)[(b * T_ >> 1) + tid];           // (zx0,zy0,zx1,zy1)

    u64 ssp = pk(__sinf(zz.x), __sinf(zz.y));
    u64 ccp = pk(__cosf(zz.x), __cosf(zz.y));
    u64 Txp = pk(ex2(kxl * zv.x), ex2(kxl * zv.z));
    u64 Typ = pk(ex2(kyl * zv.y), ex2(kyl * zv.w));
    float Lt0 = fmaf(-axl * zv.x, zv.x, fmaf(-ayl * zv.y, zv.y, LOG2_L2E));
    float Lt1 = fmaf(-axl * zv.z, zv.z, fmaf(-ayl * zv.w, zv.w, LOG2_L2E));
    u64 Ltp = pk(Lt0, Lt1);
    u64 zxp = pk(zv.x, zv.z), zyp = pk(zv.y, zv.w);

    const u64 ONEp  = pk(1.0f, 1.0f);
    const u64 HALFp = pk(0.5f, 0.5f);
    const u64 C6p   = pk(0.16666667f, 0.16666667f);
    const u64 C24p  = pk(0.041666668f, 0.041666668f);

    float* op;
    if (n0 < NTR_) op = out + (b * NTR_ + n0) * T_ + t0;
    else           op = out + B_ * NTR_ * T_ + (b * NTE_ + (n0 - NTR_)) * T_ + t0;

    unsigned cbase = (unsigned)__cvta_generic_to_shared(sC);

#pragma unroll
    for (int qi = 0; qi < NG; qi++) {
        const ulonglong2* pn = (const ulonglong2*)sN[qi];
        ulonglong2 A0 = pn[0], A1 = pn[1], A2 = pn[2], A3 = pn[3], A4 = pn[4];
        u64 Pp = A0.x, Qp = A0.y, Ap = A1.x, W0Ep = A1.y;
        u64 Rxp = A2.x, Ryp = A2.y, Pxp = A3.x, Pyp = A3.y;
        u64 Lnp = A4.x, W1p = A4.y;

        // Torus via polys: e0*w0 = W0E * exp(g), g = A*expm1(w), w = p*s+q*c
        u64 w = f2fma(Pp, ssp, f2mul(Qp, ccp));
        u64 u = f2fma(w, C24p, C6p);
        u     = f2fma(u, w, HALFp);
        u     = f2fma(u, w, ONEp);
        u64 g = f2mul(Ap, f2mul(u, w));
        u64 v = f2fma(g, C24p, C6p);
        v     = f2fma(v, g, HALFp);
        v     = f2fma(v, g, ONEp);
        u64 eg = f2fma(v, g, ONEp);            // exp(g)

        // Euclidean
        u64 txp = f2mul(Rxp, Txp);
        u64 typ = f2mul(Ryp, Typ);
        u64 lap = f2fma(Pxp, zxp, f2fma(Pyp, zyp, f2add(Lnp, Ltp)));
        float a0, a1;
        upk(lap, a0, a1);
        u64 leadp = pk(ex2(a0), ex2(a1));

        u64 c0, c1, c2, c3;
        ldsC(cbase +   0, c0, c1); ldsC(cbase +  16, c2, c3);
        u64 r0 = f2fma(f2fma(f2fma(c3, txp, c2), txp, c1), txp, c0);
        ldsC(cbase +  32, c0, c1); ldsC(cbase +  48, c2, c3);
        u64 r1 = f2fma(f2fma(f2fma(c3, txp, c2), txp, c1), txp, c0);
        ldsC(cbase +  64, c0, c1); ldsC(cbase +  80, c2, c3);
        u64 r2 = f2fma(f2fma(f2fma(c3, txp, c2), txp, c1), txp, c0);
        ldsC(cbase +  96, c0, c1); ldsC(cbase + 112, c2, c3);
        u64 r3 = f2fma(f2fma(f2fma(c3, txp, c2), txp, c1), txp, c0);
        u64 S  = f2fma(f2fma(f2fma(r3, typ, r2), typ, r1), typ, r0);

        u64 e1a = f2mul(leadp, S);
        upk(e1a, a0, a1);
        u64 e1p = pk(ex2(a0), ex2(a1));

        u64 valp = f2fma(W0Ep, eg, f2mul(W1p, e1p));
        *reinterpret_cast<u64*>(op + qi * T_) = valp;   // STG.64, coalesced
    }
}

extern "C" void kernel_launch(void* const* d_in, const int* in_sizes, int n_in,
                              void* d_out, int out_size)
{
    const float* z0       = (const float*)d_in[0];
    const float* z1       = (const float*)d_in[1];
    const float* coeff0   = (const float*)d_in[2];
    const float* mean0    = (const float*)d_in[3];
    const float* log_var0 = (const float*)d_in[4];
    const float* coeff1   = (const float*)d_in[5];
    const float* mean1    = (const float*)d_in[6];
    const float* log_var1 = (const float*)d_in[7];
    const float* rf_tr0   = (const float*)d_in[8];
    const float* rf_tr1   = (const float*)d_in[9];
    const float* rf_te0   = (const float*)d_in[10];
    const float* rf_te1   = (const float*)d_in[11];
    const float* ew_tr    = (const float*)d_in[12];
    const float* ew_te    = (const float*)d_in[13];
    const float* lfs_tr   = (const float*)d_in[14];
    const float* lfs_te   = (const float*)d_in[15];

    decoder_fused<<<B_ * (NALL / NG), 128>>>(
        z0, z1, coeff0, mean0, log_var0, coeff1, mean1, log_var1,
        rf_tr0, rf_tr1, rf_te0, rf_te1, ew_tr, ew_te, lfs_tr, lfs_te,
        (float*)d_out);
}

// round 4
// speedup vs baseline: 1.3607x; 1.3607x over previous
#include <cuda_runtime.h>

#define B_   16
#define T_   256
#define NTR_ 1024
#define NTE_ 256
#define NALL 1280
#define NG   16           // n's per block
#define NH   8            // n's per half (thread handles NH iterations)

#define L2E      1.4426950408889634f
#define LOG2_L2E 0.5287663729448977f

typedef unsigned long long u64;

__device__ __forceinline__ float ex2(float x) {
    float r; asm("ex2.approx.f32 %0, %1;" : "=f"(r) : "f"(x)); return r;
}
__device__ __forceinline__ u64 pk(float lo, float hi) {
    u64 r; asm("mov.b64 %0, {%1,%2};" : "=l"(r) : "f"(lo), "f"(hi)); return r;
}
__device__ __forceinline__ void upk(u64 v, float& lo, float& hi) {
    asm("mov.b64 {%0,%1}, %2;" : "=f"(lo), "=f"(hi) : "l"(v));
}
__device__ __forceinline__ u64 f2fma(u64 a, u64 b, u64 c) {
    u64 d; asm("fma.rn.f32x2 %0, %1, %2, %3;" : "=l"(d) : "l"(a), "l"(b), "l"(c)); return d;
}
__device__ __forceinline__ u64 f2mul(u64 a, u64 b) {
    u64 d; asm("mul.rn.f32x2 %0, %1, %2;" : "=l"(d) : "l"(a), "l"(b)); return d;
}
__device__ __forceinline__ u64 f2add(u64 a, u64 b) {
    u64 d; asm("add.rn.f32x2 %0, %1, %2;" : "=l"(d) : "l"(a), "l"(b)); return d;
}
// Volatile 128-bit shared load: guaranteed in-loop -> C table never occupies
// long-lived registers (keeps regs <= 64 for 4 blocks/SM).
__device__ __forceinline__ void ldsC(unsigned addr, u64& a, u64& b) {
    asm volatile("ld.shared.v2.u64 {%0,%1}, [%2];" : "=l"(a), "=l"(b) : "r"(addr));
}

// Block = (b, group of NG n's). 256 threads = 2 n-halves x 128 t-pair threads.
// Thread (half, tp) owns the adjacent t-pair (2*tp, 2*tp+1) packed in f32x2
// lanes and loops over NH n's of its half. Per-n constants + bicubic table in
// smem as duplicated u64 pairs.
__global__ void __launch_bounds__(256, 4)
decoder_fused(const float* __restrict__ z0,
              const float* __restrict__ z1,
              const float* __restrict__ coeff0,
              const float* __restrict__ mean0,
              const float* __restrict__ log_var0,
              const float* __restrict__ coeff1,
              const float* __restrict__ mean1,
              const float* __restrict__ log_var1,
              const float* __restrict__ rf_tr0,
              const float* __restrict__ rf_tr1,
              const float* __restrict__ rf_te0,
              const float* __restrict__ rf_te1,
              const float* __restrict__ ew_tr,
              const float* __restrict__ ew_te,
              const float* __restrict__ lfs_tr,
              const float* __restrict__ lfs_te,
              float* __restrict__ out)
{
    __shared__ float4 sN[NG][5];   // per-n consts, duplicated pairs
    __shared__ u64    sC[16];      // bicubic coeffs, duplicated pairs
    __shared__ float  sG[4];       // kxl, kyl, axl, ayl

    const int tid = threadIdx.x;
    const int bid = blockIdx.x;
    const int b   = bid / (NALL / NG);
    const int ng  = bid % (NALL / NG);
    const int n0  = ng * NG;

    // ---- in-block constant prep ----
    if (tid < NG) {
        int n = n0 + tid;
        int nn; const float *rf0, *rf1, *ew, *lfs;
        if (n < NTR_) { nn = n;        rf0 = rf_tr0; rf1 = rf_tr1; ew = ew_tr; lfs = lfs_tr; }
        else          { nn = n - NTR_; rf0 = rf_te0; rf1 = rf_te1; ew = ew_te; lfs = lfs_te; }

        // Torus (K0=1,L0=1): e0 = exp2(AL * exp2(P*s + Q*c))
        float mu  = mean0[0];
        float ms  = sinf(mu) - sinf(rf0[nn]);
        float mc  = cosf(mu) - cosf(rf0[nn]);
        float v0  = expf(log_var0[0]);
        float iv0 = 1.0f / (v0 * v0);
        float P   = 2.0f * ms * iv0 * L2E;
        float Q   = 2.0f * mc * iv0 * L2E;
        float A   = coeff0[0] * expf(-(1.0f + ms * ms + mc * mc) * iv0);
        float AL  = A * L2E;

        float e0w = ew[nn * 2], e1w = ew[nn * 2 + 1];
        float mx  = fmaxf(e0w, e1w);
        float ea  = expf(e0w - mx), eb = expf(e1w - mx);
        float scl = expf(lfs[nn]) / (ea + eb);
        float w0  = ea * scl, w1 = eb * scl;

        float dx  = mean1[8] - mean1[0];
        float dy  = mean1[3] - mean1[1];
        float vx  = expf(log_var1[0]), vy = expf(log_var1[1]);
        float ivx = 1.0f / (vx * vx),  ivy = 1.0f / (vy * vy);
        float axl = ivx * L2E,         ayl = ivy * L2E;
        float kxl = 2.0f * dx * ivx * L2E, kyl = 2.0f * dy * ivy * L2E;
        float rx  = rf1[nn * 2 + 0] - mean1[0];
        float ry  = rf1[nn * 2 + 1] - mean1[1];
        float Rx  = exp2f(kxl * rx), Ry = exp2f(kyl * ry);
        float Px  = -2.0f * axl * rx, Py = -2.0f * ayl * ry;
        float Ln  = -axl * rx * rx - ayl * ry * ry;

        sN[tid][0] = make_float4(P,  P,  Q,  Q);
        sN[tid][1] = make_float4(AL, AL, w0, w0);
        sN[tid][2] = make_float4(Rx, Rx, Ry, Ry);
        sN[tid][3] = make_float4(Px, Px, Py, Py);
        sN[tid][4] = make_float4(Ln, Ln, w1, w1);
    } else if (tid >= 32 && tid < 48) {
        int e = tid - 32;
        int i = e & 3, j = e >> 2;
        float dx  = mean1[8] - mean1[0];
        float dy  = mean1[3] - mean1[1];
        float vx  = expf(log_var1[0]), vy = expf(log_var1[1]);
        float ivx = 1.0f / (vx * vx),  ivy = 1.0f / (vy * vy);
        float v = coeff1[i * 4 + j] *
                  expf(-(float)(i * i) * dx * dx * ivx - (float)(j * j) * dy * dy * ivy);
        sC[e] = pk(v, v);
    } else if (tid == 64) {
        float dx  = mean1[8] - mean1[0];
        float dy  = mean1[3] - mean1[1];
        float vx  = expf(log_var1[0]), vy = expf(log_var1[1]);
        float ivx = 1.0f / (vx * vx),  ivy = 1.0f / (vy * vy);
        sG[0] = 2.0f * dx * ivx * L2E;   // kxl
        sG[1] = 2.0f * dy * ivy * L2E;   // kyl
        sG[2] = ivx * L2E;               // axl
        sG[3] = ivy * L2E;               // ayl
    }
    __syncthreads();

    const int tp   = tid & 127;         // t-pair index
    const int half = tid >> 7;          // which NH-group of n
    const int nb   = half * NH;         // smem n offset

    const float kxl = sG[0], kyl = sG[1], axl = sG[2], ayl = sG[3];

    // ---- per-thread adjacent t-pair terms ----
    float2 zz = ((const float2*)z0)[b * (T_ / 2) + tp];     // z0[2tp], z0[2tp+1]
    float4 zv = ((const float4*)z1)[b * (T_ / 2) + tp];     // (zx0,zy0,zx1,zy1)

    u64 ssp = pk(__sinf(zz.x), __sinf(zz.y));
    u64 ccp = pk(__cosf(zz.x), __cosf(zz.y));
    u64 Txp = pk(ex2(kxl * zv.x), ex2(kxl * zv.z));
    u64 Typ = pk(ex2(kyl * zv.y), ex2(kyl * zv.w));
    float Lt0 = fmaf(-axl * zv.x, zv.x, fmaf(-ayl * zv.y, zv.y, LOG2_L2E));
    float Lt1 = fmaf(-axl * zv.z, zv.z, fmaf(-ayl * zv.w, zv.w, LOG2_L2E));
    u64 Ltp = pk(Lt0, Lt1);
    u64 zxp = pk(zv.x, zv.z), zyp = pk(zv.y, zv.w);

    const int nstart = n0 + nb;
    float* op;
    if (n0 < NTR_) op = out + (b * NTR_ + nstart) * T_ + 2 * tp;
    else           op = out + B_ * NTR_ * T_ + (b * NTE_ + (nstart - NTR_)) * T_ + 2 * tp;

    unsigned cbase = (unsigned)__cvta_generic_to_shared(sC);

#pragma unroll
    for (int qi = 0; qi < NH; qi++) {
        const ulonglong2* pn = (const ulonglong2*)sN[nb + qi];
        ulonglong2 A0 = pn[0], A1 = pn[1], A2 = pn[2], A3 = pn[3], A4 = pn[4];
        u64 Pp = A0.x, Qp = A0.y, ALp = A1.x, W0p = A1.y;
        u64 Rxp = A2.x, Ryp = A2.y, Pxp = A3.x, Pyp = A3.y;
        u64 Lnp = A4.x, W1p = A4.y;

        float a0, a1;

        // Torus: e0 = exp2(AL * exp2(P*s + Q*c))
        u64 targ = f2fma(Pp, ssp, f2mul(Qp, ccp));
        upk(targ, a0, a1);
        u64 t0p = pk(ex2(a0), ex2(a1));
        u64 e0a = f2mul(ALp, t0p);
        upk(e0a, a0, a1);
        u64 e0p = pk(ex2(a0), ex2(a1));

        // Euclidean: tx/ty via per-n factors, lead via split exponent
        u64 txp = f2mul(Rxp, Txp);
        u64 typ = f2mul(Ryp, Typ);
        u64 lap = f2fma(Pxp, zxp, f2fma(Pyp, zyp, f2add(Lnp, Ltp)));
        upk(lap, a0, a1);
        u64 leadp = pk(ex2(a0), ex2(a1));

        // bicubic Horner in tx (rows), then ty
        u64 c0, c1, c2, c3;
        ldsC(cbase +   0, c0, c1); ldsC(cbase +  16, c2, c3);
        u64 r0 = f2fma(f2fma(f2fma(c3, txp, c2), txp, c1), txp, c0);
        ldsC(cbase +  32, c0, c1); ldsC(cbase +  48, c2, c3);
        u64 r1 = f2fma(f2fma(f2fma(c3, txp, c2), txp, c1), txp, c0);
        ldsC(cbase +  64, c0, c1); ldsC(cbase +  80, c2, c3);
        u64 r2 = f2fma(f2fma(f2fma(c3, txp, c2), txp, c1), txp, c0);
        ldsC(cbase +  96, c0, c1); ldsC(cbase + 112, c2, c3);
        u64 r3 = f2fma(f2fma(f2fma(c3, txp, c2), txp, c1), txp, c0);
        u64 S  = f2fma(f2fma(f2fma(r3, typ, r2), typ, r1), typ, r0);

        u64 e1a = f2mul(leadp, S);
        upk(e1a, a0, a1);
        u64 e1p = pk(ex2(a0), ex2(a1));

        u64 valp = f2fma(W0p, e0p, f2mul(W1p, e1p));
        *reinterpret_cast<u64*>(op + qi * T_) = valp;   // STG.64, coalesced
    }
}

extern "C" void kernel_launch(void* const* d_in, const int* in_sizes, int n_in,
                              void* d_out, int out_size)
{
    const float* z0       = (const float*)d_in[0];
    const float* z1       = (const float*)d_in[1];
    const float* coeff0   = (const float*)d_in[2];
    const float* mean0    = (const float*)d_in[3];
    const float* log_var0 = (const float*)d_in[4];
    const float* coeff1   = (const float*)d_in[5];
    const float* mean1    = (const float*)d_in[6];
    const float* log_var1 = (const float*)d_in[7];
    const float* rf_tr0   = (const float*)d_in[8];
    const float* rf_tr1   = (const float*)d_in[9];
    const float* rf_te0   = (const float*)d_in[10];
    const float* rf_te1   = (const float*)d_in[11];
    const float* ew_tr    = (const float*)d_in[12];
    const float* ew_te    = (const float*)d_in[13];
    const float* lfs_tr   = (const float*)d_in[14];
    const float* lfs_te   = (const float*)d_in[15];

    decoder_fused<<<B_ * (NALL / NG), 256>>>(
        z0, z1, coeff0, mean0, log_var0, coeff1, mean1, log_var1,
        rf_tr0, rf_tr1, rf_te0, rf_te1, ew_tr, ew_te, lfs_tr, lfs_te,
        (float*)d_out);
}

// round 5
// speedup vs baseline: 1.5656x; 1.1505x over previous
#include <cuda_runtime.h>

#define B_   16
#define T_   256
#define NTR_ 1024
#define NTE_ 256
#define NALL 1280
#define NG   16           // n's per block
#define NH   8            // n's per half (thread handles NH iterations)

#define L2E      1.4426950408889634f
#define LOG2_L2E 0.5287663729448977f

typedef unsigned long long u64;

__device__ __forceinline__ float ex2(float x) {
    float r; asm("ex2.approx.f32 %0, %1;" : "=f"(r) : "f"(x)); return r;
}
__device__ __forceinline__ u64 pk(float lo, float hi) {
    u64 r; asm("mov.b64 %0, {%1,%2};" : "=l"(r) : "f"(lo), "f"(hi)); return r;
}
__device__ __forceinline__ void upk(u64 v, float& lo, float& hi) {
    asm("mov.b64 {%0,%1}, %2;" : "=f"(lo), "=f"(hi) : "l"(v));
}
__device__ __forceinline__ u64 f2fma(u64 a, u64 b, u64 c) {
    u64 d; asm("fma.rn.f32x2 %0, %1, %2, %3;" : "=l"(d) : "l"(a), "l"(b), "l"(c)); return d;
}
__device__ __forceinline__ u64 f2mul(u64 a, u64 b) {
    u64 d; asm("mul.rn.f32x2 %0, %1, %2;" : "=l"(d) : "l"(a), "l"(b)); return d;
}
__device__ __forceinline__ u64 f2add(u64 a, u64 b) {
    u64 d; asm("add.rn.f32x2 %0, %1, %2;" : "=l"(d) : "l"(a), "l"(b)); return d;
}
// Volatile 128-bit shared load: guaranteed in-loop -> C table never occupies
// long-lived registers (keeps regs <= 64 for 4 blocks/SM).
__device__ __forceinline__ void ldsC(unsigned addr, u64& a, u64& b) {
    asm volatile("ld.shared.v2.u64 {%0,%1}, [%2];" : "=l"(a), "=l"(b) : "r"(addr));
}

// Block = (b, group of NG n's). 256 threads = 2 n-halves x 128 t-pair threads.
// Thread (half, tp) owns the adjacent t-pair (2*tp, 2*tp+1) packed in f32x2
// lanes and loops over NH n's of its half.
__global__ void __launch_bounds__(256, 4)
decoder_fused(const float* __restrict__ z0,
              const float* __restrict__ z1,
              const float* __restrict__ coeff0,
              const float* __restrict__ mean0,
              const float* __restrict__ log_var0,
              const float* __restrict__ coeff1,
              const float* __restrict__ mean1,
              const float* __restrict__ log_var1,
              const float* __restrict__ rf_tr0,
              const float* __restrict__ rf_tr1,
              const float* __restrict__ rf_te0,
              const float* __restrict__ rf_te1,
              const float* __restrict__ ew_tr,
              const float* __restrict__ ew_te,
              const float* __restrict__ lfs_tr,
              const float* __restrict__ lfs_te,
              float* __restrict__ out)
{
    __shared__ float4 sN[NG][5];   // per-n consts, duplicated pairs
    __shared__ u64    sC[16];      // bicubic coeffs, duplicated pairs

    const int tid = threadIdx.x;
    const int bid = blockIdx.x;
    const int b   = bid / (NALL / NG);
    const int ng  = bid % (NALL / NG);
    const int n0  = ng * NG;

    // Global scalars every thread needs (broadcast loads, fast-math).
    const float dx  = mean1[8] - mean1[0];
    const float dy  = mean1[3] - mean1[1];
    const float ivx = __expf(-2.0f * log_var1[0]);  // 1/vx^2
    const float ivy = __expf(-2.0f * log_var1[1]);
    const float axl = ivx * L2E, ayl = ivy * L2E;
    const float kxl = 2.0f * dx * axl, kyl = 2.0f * dy * ayl;

    // ---- in-block constant prep (fast-math intrinsics only) ----
    if (tid < NG) {
        int n = n0 + tid;
        int nn; const float *rf0, *rf1, *ew, *lfs;
        if (n < NTR_) { nn = n;        rf0 = rf_tr0; rf1 = rf_tr1; ew = ew_tr; lfs = lfs_tr; }
        else          { nn = n - NTR_; rf0 = rf_te0; rf1 = rf_te1; ew = ew_te; lfs = lfs_te; }

        // Torus (K0=1,L0=1): w0*e0 = exp2(AL*exp(w) + LW0), w = p*s + q*c
        float mu  = mean0[0];
        float smu, cmu, sr, cr;
        __sincosf(mu, &smu, &cmu);
        __sincosf(rf0[nn], &sr, &cr);
        float ms  = smu - sr;
        float mc  = cmu - cr;
        float iv0 = __expf(-2.0f * log_var0[0]);
        float p   = 2.0f * ms * iv0;
        float q   = 2.0f * mc * iv0;
        float A   = coeff0[0] * __expf(-(1.0f + ms * ms + mc * mc) * iv0);
        float AL  = A * L2E;

        float e0w = ew[nn * 2], e1w = ew[nn * 2 + 1];
        float mx  = fmaxf(e0w, e1w);
        float ea  = __expf(e0w - mx), eb = __expf(e1w - mx);
        float scl = __expf(lfs[nn]) / (ea + eb);
        float LW0 = __log2f(ea * scl);
        float LW1 = __log2f(eb * scl);
        float ALW0 = AL + LW0;

        float rx  = rf1[nn * 2 + 0] - mean1[0];
        float ry  = rf1[nn * 2 + 1] - mean1[1];
        float Rx  = ex2(kxl * rx), Ry = ex2(kyl * ry);
        float Px  = -2.0f * axl * rx, Py = -2.0f * ayl * ry;
        float Ln  = -axl * rx * rx - ayl * ry * ry;

        sN[tid][0] = make_float4(p,  p,  q,    q);
        sN[tid][1] = make_float4(AL, AL, ALW0, ALW0);
        sN[tid][2] = make_float4(Rx, Rx, Ry,   Ry);
        sN[tid][3] = make_float4(Px, Px, Py,   Py);
        sN[tid][4] = make_float4(Ln, Ln, LW1,  LW1);
    } else if (tid >= 32 && tid < 48) {
        int e = tid - 32;
        int i = e & 3, j = e >> 2;
        float v = coeff1[i * 4 + j] *
                  __expf(-(float)(i * i) * dx * dx * ivx - (float)(j * j) * dy * dy * ivy);
        sC[e] = pk(v, v);
    }
    __syncthreads();

    const int tp   = tid & 127;         // t-pair index
    const int half = tid >> 7;          // which NH-group of n
    const int nb   = half * NH;         // smem n offset

    // ---- per-thread adjacent t-pair terms ----
    float2 zz = ((const float2*)z0)[b * (T_ / 2) + tp];     // z0[2tp], z0[2tp+1]
    float4 zv = ((const float4*)z1)[b * (T_ / 2) + tp];     // (zx0,zy0,zx1,zy1)

    float s0, c0, s1, c1;
    __sincosf(zz.x, &s0, &c0);
    __sincosf(zz.y, &s1, &c1);
    u64 ssp = pk(s0, s1);
    u64 ccp = pk(c0, c1);
    u64 Txp = pk(ex2(kxl * zv.x), ex2(kxl * zv.z));
    u64 Typ = pk(ex2(kyl * zv.y), ex2(kyl * zv.w));
    float Lt0 = fmaf(-axl * zv.x, zv.x, fmaf(-ayl * zv.y, zv.y, LOG2_L2E));
    float Lt1 = fmaf(-axl * zv.z, zv.z, fmaf(-ayl * zv.w, zv.w, LOG2_L2E));
    u64 Ltp = pk(Lt0, Lt1);
    u64 zxp = pk(zv.x, zv.z), zyp = pk(zv.y, zv.w);

    const u64 HALFp = pk(0.5f, 0.5f);
    const u64 C6p   = pk(0.16666667f, 0.16666667f);

    const int nstart = n0 + nb;
    float* op;
    if (n0 < NTR_) op = out + (b * NTR_ + nstart) * T_ + 2 * tp;
    else           op = out + B_ * NTR_ * T_ + (b * NTE_ + (nstart - NTR_)) * T_ + 2 * tp;

    unsigned cbase = (unsigned)__cvta_generic_to_shared(sC);

#pragma unroll
    for (int qi = 0; qi < NH; qi++) {
        const ulonglong2* pn = (const ulonglong2*)sN[nb + qi];
        ulonglong2 A0 = pn[0], A1 = pn[1], A2 = pn[2], A3 = pn[3], A4 = pn[4];
        u64 Pp = A0.x, Qp = A0.y, ALp = A1.x, ALW0p = A1.y;
        u64 Rxp = A2.x, Ryp = A2.y, Pxp = A3.x, Pyp = A3.y;
        u64 Lnp = A4.x, LW1p = A4.y;

        float a0, a1;

        // Torus: w small (|w|<=0.06): exp(w)-1 = w*(1 + w*(1/2 + w/6))
        // w0*e0 = exp2(AL*exp(w) + LW0) = exp2(ALw*g2 + (ALw + ALW0)),
        //   where ALw = AL*w, g2 = w*(1/2 + w/6) ... since AL*exp(w) =
        //   AL + AL*w + AL*w*g2.
        u64 w    = f2fma(Pp, ssp, f2mul(Qp, ccp));
        u64 v    = f2fma(w, C6p, HALFp);
        u64 g2   = f2mul(w, v);
        u64 ALw  = f2mul(ALp, w);
        u64 e0b  = f2add(ALw, ALW0p);
        u64 e0g  = f2fma(ALw, g2, e0b);
        upk(e0g, a0, a1);
        u64 e0p = pk(ex2(a0), ex2(a1));            // = w0 * e0

        // Euclidean: tx/ty via per-n factors, lead via split exponent
        u64 txp = f2mul(Rxp, Txp);
        u64 typ = f2mul(Ryp, Typ);
        u64 lap = f2fma(Pxp, zxp, f2fma(Pyp, zyp, f2add(Lnp, Ltp)));
        upk(lap, a0, a1);
        u64 leadp = pk(ex2(a0), ex2(a1));

        // bicubic Horner in tx (rows), then ty
        u64 c0r, c1r, c2r, c3r;
        ldsC(cbase +   0, c0r, c1r); ldsC(cbase +  16, c2r, c3r);
        u64 r0 = f2fma(f2fma(f2fma(c3r, txp, c2r), txp, c1r), txp, c0r);
        ldsC(cbase +  32, c0r, c1r); ldsC(cbase +  48, c2r, c3r);
        u64 r1 = f2fma(f2fma(f2fma(c3r, txp, c2r), txp, c1r), txp, c0r);
        ldsC(cbase +  64, c0r, c1r); ldsC(cbase +  80, c2r, c3r);
        u64 r2 = f2fma(f2fma(f2fma(c3r, txp, c2r), txp, c1r), txp, c0r);
        ldsC(cbase +  96, c0r, c1r); ldsC(cbase + 112, c2r, c3r);
        u64 r3 = f2fma(f2fma(f2fma(c3r, txp, c2r), txp, c1r), txp, c0r);
        u64 S  = f2fma(f2fma(f2fma(r3, typ, r2), typ, r1), typ, r0);

        // w1*e1 = exp2(lead*S + LW1)
        u64 e1g = f2fma(leadp, S, LW1p);
        upk(e1g, a0, a1);
        u64 e1p = pk(ex2(a0), ex2(a1));

        u64 valp = f2add(e0p, e1p);
        *reinterpret_cast<u64*>(op + qi * T_) = valp;   // STG.64, coalesced
    }
}

extern "C" void kernel_launch(void* const* d_in, const int* in_sizes, int n_in,
                              void* d_out, int out_size)
{
    const float* z0       = (const float*)d_in[0];
    const float* z1       = (const float*)d_in[1];
    const float* coeff0   = (const float*)d_in[2];
    const float* mean0    = (const float*)d_in[3];
    const float* log_var0 = (const float*)d_in[4];
    const float* coeff1   = (const float*)d_in[5];
    const float* mean1    = (const float*)d_in[6];
    const float* log_var1 = (const float*)d_in[7];
    const float* rf_tr0   = (const float*)d_in[8];
    const float* rf_tr1   = (const float*)d_in[9];
    const float* rf_te0   = (const float*)d_in[10];
    const float* rf_te1   = (const float*)d_in[11];
    const float* ew_tr    = (const float*)d_in[12];
    const float* ew_te    = (const float*)d_in[13];
    const float* lfs_tr   = (const float*)d_in[14];
    const float* lfs_te   = (const float*)d_in[15];

    decoder_fused<<<B_ * (NALL / NG), 256>>>(
        z0, z1, coeff0, mean0, log_var0, coeff1, mean1, log_var1,
        rf_tr0, rf_tr1, rf_te0, rf_te1, ew_tr, ew_te, lfs_tr, lfs_te,
        (float*)d_out);
}